// round 14
// baseline (speedup 1.0000x reference)
#include <cuda_runtime.h>
#include <math.h>

#define NSEQ 64
static constexpr int LA  = 2305;   // run0 length (1 gt + 48*48)
static constexpr int LB  = 3073;   // run1/2 length (1 gt + 128*24)
static constexpr int LPA = 2336;   // padded strides (mult of 32)
static constexpr int LPB = 3104;
static constexpr int LTA = 2304;   // output token counts (mult of 32)
static constexpr int LTB = 3072;

// ---------- scratch (device globals; allocation-free) ----------
__device__ __align__(16) float gA_xz [NSEQ*LA*128];
__device__ __align__(16) float gA_dtT[NSEQ*64*LPA];
__device__ __align__(16) float gA_xsT[NSEQ*64*LPA];
__device__ __align__(16) float gA_zsT[NSEQ*64*LPA];
__device__ __align__(16) float gA_bcI[NSEQ*32*LPA];   // [n][tb][comp32][4]
__device__ __align__(16) float gA_yT [NSEQ*64*LTA];   // [n][ch][t]
__device__ __align__(16) float gA_o  [NSEQ*LTA*32];

__device__ __align__(16) float gB_xz0 [NSEQ*LB*96];
__device__ __align__(16) float gB_dtT0[NSEQ*48*LPB];
__device__ __align__(16) float gB_xsT0[NSEQ*48*LPB];
__device__ __align__(16) float gB_zsT0[NSEQ*48*LPB];
__device__ __align__(16) float gB_bcI0[NSEQ*32*LPB];
__device__ __align__(16) float gB_yT0 [NSEQ*48*LTB];
__device__ __align__(16) float gB_o0  [NSEQ*LTB*24];

__device__ __align__(16) float gB_xz1 [NSEQ*LB*96];
__device__ __align__(16) float gB_dtT1[NSEQ*48*LPB];
__device__ __align__(16) float gB_xsT1[NSEQ*48*LPB];
__device__ __align__(16) float gB_zsT1[NSEQ*48*LPB];
__device__ __align__(16) float gB_bcI1[NSEQ*32*LPB];
__device__ __align__(16) float gB_yT1 [NSEQ*48*LTB];
__device__ __align__(16) float gB_o1  [NSEQ*LTB*24];

template<int RUN> __device__ __forceinline__ float* bufXZ(){
  if constexpr (RUN==0) return gA_xz; else if constexpr (RUN==1) return gB_xz0; else return gB_xz1; }
template<int RUN> __device__ __forceinline__ float* bufDTT(){
  if constexpr (RUN==0) return gA_dtT; else if constexpr (RUN==1) return gB_dtT0; else return gB_dtT1; }
template<int RUN> __device__ __forceinline__ float* bufXST(){
  if constexpr (RUN==0) return gA_xsT; else if constexpr (RUN==1) return gB_xsT0; else return gB_xsT1; }
template<int RUN> __device__ __forceinline__ float* bufZST(){
  if constexpr (RUN==0) return gA_zsT; else if constexpr (RUN==1) return gB_zsT0; else return gB_zsT1; }
template<int RUN> __device__ __forceinline__ float* bufBCI(){
  if constexpr (RUN==0) return gA_bcI; else if constexpr (RUN==1) return gB_bcI0; else return gB_bcI1; }
template<int RUN> __device__ __forceinline__ float* bufYT(){
  if constexpr (RUN==0) return gA_yT; else if constexpr (RUN==1) return gB_yT0; else return gB_yT1; }
template<int RUN> __device__ __forceinline__ float* bufO(){
  if constexpr (RUN==0) return gA_o; else if constexpr (RUN==1) return gB_o0; else return gB_o1; }

__device__ __forceinline__ float warp_sum(float v){
  v += __shfl_xor_sync(0xffffffffu, v, 16);
  v += __shfl_xor_sync(0xffffffffu, v, 8);
  v += __shfl_xor_sync(0xffffffffu, v, 4);
  v += __shfl_xor_sync(0xffffffffu, v, 2);
  v += __shfl_xor_sync(0xffffffffu, v, 1);
  return v;
}
__device__ __forceinline__ float silu_f(float x){
  return __fdividef(x, 1.f + __expf(-x));
}

// ---------- packed f32x2 helpers ----------
__device__ __forceinline__ unsigned long long pack2(float lo, float hi){
  unsigned long long r;
  asm("mov.b64 %0, {%1, %2};" : "=l"(r) : "f"(lo), "f"(hi));
  return r;
}
__device__ __forceinline__ float2 unpack2(unsigned long long v){
  float2 f;
  asm("mov.b64 {%0, %1}, %2;" : "=f"(f.x), "=f"(f.y) : "l"(v));
  return f;
}
__device__ __forceinline__ void ffma2(unsigned long long &d, unsigned long long a, unsigned long long b){
  asm("fma.rn.f32x2 %0, %1, %2, %0;" : "+l"(d) : "l"(a), "l"(b));
}

// ============ K1: gather + layernorm + in_proj (FFMA2) ============
template<int RUN>
__global__ void __launch_bounds__(128) k_inproj(
    const float* __restrict__ x, const float* __restrict__ nw,
    const float* __restrict__ nb, const float* __restrict__ gt,
    const float* __restrict__ Win)
{
  constexpr int DM  = (RUN==0)?32:24;
  constexpr int DXZ = (RUN==0)?128:96;
  constexpr int LF  = (RUN==0)?LA:LB;
  constexpr int KO  = DXZ/32;
  __shared__ float Wtr[DM*128];                   // [d][lane][4] (k padded to 4)
  __shared__ __align__(16) float vsh[4][DM][8];

  int tid = threadIdx.x;
  for (int i = tid; i < DM*128; i += 128){
    int d = i >> 7, r = i & 127, ln = r >> 2, k = r & 3;
    Wtr[i] = (k < KO) ? Win[(k*32+ln)*DM + d] : 0.f;
  }
  int w = tid >> 5, lane = tid & 31;
  int n = blockIdx.y, bh = n >> 3, bw = n & 7;
  int t0 = (blockIdx.x*4 + w)*8;

  float v[8];
  #pragma unroll
  for (int tok = 0; tok < 8; tok++){
    int t = t0 + tok; float val = 0.f;
    if (lane < DM && t < LF){
      if (t == 0) val = gt[lane];
      else {
        int q = t - 1, addr;
        if (RUN == 0){
          int row = q / 48, col = q - row*48;
          int i0 = row >> 1, r1 = row & 1, j0 = col >> 1, r2 = col & 1;
          addr = (lane*4 + r1*2 + r2)*36864 + (bh*24 + i0)*192 + bw*24 + j0;
        } else if (RUN == 1){
          int c = q / 24, p = q - c*24;
          addr = c*36864 + (bh*24 + lane)*192 + bw*24 + p;
        } else {
          int c = q / 24, p = q - c*24;
          addr = c*36864 + (bh*24 + p)*192 + bw*24 + lane;
        }
        val = __ldg(x + addr);
      }
    }
    v[tok] = val;
  }
  float nwv = (lane < DM) ? nw[lane] : 0.f;
  float nbv = (lane < DM) ? nb[lane] : 0.f;
  #pragma unroll
  for (int tok = 0; tok < 8; tok++){
    float s  = warp_sum(v[tok]);
    float s2 = warp_sum(v[tok]*v[tok]);
    float m  = s * (1.f/DM);
    float var = s2 * (1.f/DM) - m*m;
    float vn = (v[tok] - m) * rsqrtf(var + 1e-5f) * nwv + nbv;
    if (lane < DM) vsh[w][lane][tok] = vn;
  }
  __syncthreads();

  unsigned long long accp[KO][4];
  #pragma unroll
  for (int k = 0; k < KO; k++)
    #pragma unroll
    for (int p = 0; p < 4; p++) accp[k][p] = 0ull;

  #pragma unroll 4
  for (int d = 0; d < DM; d++){
    const ulonglong2* vp = (const ulonglong2*)vsh[w][d];
    ulonglong2 va = vp[0], vb = vp[1];
    float4 wq = *(const float4*)&Wtr[(d*32+lane)*4];
    float wa[4] = {wq.x, wq.y, wq.z, wq.w};
    #pragma unroll
    for (int k = 0; k < KO; k++){
      unsigned long long wp = pack2(wa[k], wa[k]);
      ffma2(accp[k][0], wp, va.x);
      ffma2(accp[k][1], wp, va.y);
      ffma2(accp[k][2], wp, vb.x);
      ffma2(accp[k][3], wp, vb.y);
    }
  }
  float* xz = bufXZ<RUN>();
  #pragma unroll
  for (int p = 0; p < 4; p++){
    float2 f[KO];
    #pragma unroll
    for (int k = 0; k < KO; k++) f[k] = unpack2(accp[k][p]);
    #pragma unroll
    for (int e = 0; e < 2; e++){
      int t = t0 + 2*p + e;
      if (t < LF){
        float* op = xz + (n*LF + t)*DXZ + lane;
        #pragma unroll
        for (int k = 0; k < KO; k++) op[32*k] = e ? f[k].y : f[k].x;
      }
    }
  }
}

// ============ K2: conv + silu + x_proj + dt (FFMA2 xproj) ============
template<int RUN>
__global__ void __launch_bounds__(256) k_convxp(
  const float* __restrict__ convw, const float* __restrict__ convb,
  const float* __restrict__ Wx,    const float* __restrict__ dtw,
  const float* __restrict__ dtb)
{
  constexpr int DIN = (RUN==0)?64:48;
  constexpr int DXZ = 2*DIN;
  constexpr int LF  = (RUN==0)?LA:LB;
  constexpr int LFP = (RUN==0)?LPA:LPB;
  const float* xz = bufXZ<RUN>();
  float* xsT = bufXST<RUN>();
  float* zsT = bufZST<RUN>();
  float* dtT = bufDTT<RUN>();
  float* bcI = bufBCI<RUN>();

  __shared__ float Wxt[DIN*34];          // [d][o]
  __shared__ __align__(16) float xs_s[DIN][34];
  __shared__ __align__(16) float zs_s[DIN][34];
  __shared__ __align__(16) float dt_s[DIN][34];
  __shared__ float bc_s[32][33];

  int tid = threadIdx.x;
  for (int i = tid; i < 34*DIN; i += 256){
    int o = i / DIN, d = i - o*DIN;
    Wxt[d*34 + o] = Wx[i];
  }
  int w = tid >> 5, lane = tid & 31;
  int n = blockIdx.y;
  int tile0 = blockIdx.x*32;
  int t0 = tile0 + w*4;

  float cw[2][4], cb[2], w0c[2], w1c[2], db[2];
  #pragma unroll
  for (int kk = 0; kk < 2; kk++){
    int ch = lane + 32*kk;
    bool ok = ch < DIN;
    #pragma unroll
    for (int k = 0; k < 4; k++) cw[kk][k] = ok ? convw[ch*4+k] : 0.f;
    cb[kk]  = ok ? convb[ch]   : 0.f;
    w0c[kk] = ok ? dtw[ch*2+0] : 0.f;
    w1c[kk] = ok ? dtw[ch*2+1] : 0.f;
    db[kk]  = ok ? dtb[ch]     : 0.f;
  }
  #pragma unroll
  for (int tok = 0; tok < 4; tok++){
    int t = t0 + tok;
    bool valid = t < LF;
    #pragma unroll
    for (int kk = 0; kk < 2; kk++){
      int ch = lane + 32*kk;
      if (ch < DIN){
        float a = cb[kk];
        float zval = 0.f;
        if (valid){
          #pragma unroll
          for (int k = 0; k < 4; k++){
            int ts = t + k - 3;
            if (ts >= 0) a = fmaf(xz[(n*LF + ts)*DXZ + ch], cw[kk][k], a);
          }
          zval = xz[(n*LF + t)*DXZ + DIN + ch];
        }
        xs_s[ch][w*4+tok] = silu_f(a);
        zs_s[ch][w*4+tok] = silu_f(zval);
      }
    }
  }
  __syncthreads();   // Wxt + xs_s ready

  unsigned long long ap0=0ull, ap1=0ull, a2p0=0ull, a2p1=0ull;
  #pragma unroll 8
  for (int d = 0; d < DIN; d++){
    const unsigned long long* xp = (const unsigned long long*)&xs_s[d][w*4];
    unsigned long long x01 = xp[0], x23 = xp[1];
    float wv = Wxt[d*34 + lane];
    unsigned long long wp = pack2(wv, wv);
    ffma2(ap0, wp, x01);
    ffma2(ap1, wp, x23);
    if (lane < 2){
      float w2 = Wxt[d*34 + 32 + lane];
      unsigned long long wp2 = pack2(w2, w2);
      ffma2(a2p0, wp2, x01);
      ffma2(a2p1, wp2, x23);
    }
  }
  float2 u0 = unpack2(ap0), u1 = unpack2(ap1);
  float acc[4]  = {u0.x, u0.y, u1.x, u1.y};
  float2 q0 = unpack2(a2p0), q1 = unpack2(a2p1);
  float acc2[4] = {q0.x, q0.y, q1.x, q1.y};

  #pragma unroll
  for (int tok = 0; tok < 4; tok++){
    float d0 = __shfl_sync(0xffffffffu, acc[tok], 0);
    float d1 = __shfl_sync(0xffffffffu, acc[tok], 1);
    #pragma unroll
    for (int kk = 0; kk < 2; kk++){
      int ch = lane + 32*kk;
      if (ch < DIN){
        float r = fmaf(w0c[kk], d0, fmaf(w1c[kk], d1, db[kk]));
        dt_s[ch][w*4+tok] = fmaxf(r, 0.f) + __logf(1.f + __expf(-fabsf(r)));
      }
    }
    if (lane >= 2) bc_s[lane-2][w*4+tok]  = acc[tok];
    else           bc_s[30+lane][w*4+tok] = acc2[tok];
  }
  __syncthreads();

  // coalesced flush: consecutive threads -> consecutive float4 along t
  for (int i = tid; i < DIN*8; i += 256){
    int ch = i >> 3, v = i & 7;
    int tt = tile0 + 4*v;
    size_t off = (size_t)(n*DIN + ch)*LFP + tt;
    *(float4*)(xsT + off) = make_float4(xs_s[ch][4*v],xs_s[ch][4*v+1],xs_s[ch][4*v+2],xs_s[ch][4*v+3]);
    *(float4*)(zsT + off) = make_float4(zs_s[ch][4*v],zs_s[ch][4*v+1],zs_s[ch][4*v+2],zs_s[ch][4*v+3]);
    *(float4*)(dtT + off) = make_float4(dt_s[ch][4*v],dt_s[ch][4*v+1],dt_s[ch][4*v+2],dt_s[ch][4*v+3]);
  }
  // bc interleaved flush: [n][tb][comp][4]
  {
    int tbl = tid >> 5, comp = tid & 31;
    float4 bv = make_float4(bc_s[comp][4*tbl],bc_s[comp][4*tbl+1],bc_s[comp][4*tbl+2],bc_s[comp][4*tbl+3]);
    *(float4*)(bcI + ((size_t)(n*(LFP/4) + tile0/4 + tbl)*32 + comp)*4) = bv;
  }
}

// ============ K3a: A-run scan (8 lanes/ch, 2 states/lane, 8 tok/iter) ============
template<int L, int DIN, int LFP, int LT>
__device__ __forceinline__ void scan8u2(
  const float* __restrict__ dtT, const float* __restrict__ xsT,
  const float* __restrict__ zsT, const float* __restrict__ bcI,
  float* __restrict__ yT, const float* __restrict__ alog,
  const float* __restrict__ Dv, int n, int ch4, int lane)
{
  int g = lane >> 3, s = lane & 7;
  int ch = ch4 + g;
  const float* dtp = dtT + (size_t)(n*DIN + ch)*LFP;
  const float* xsp = xsT + (size_t)(n*DIN + ch)*LFP;
  const float* zsp = zsT + (size_t)(n*DIN + ch)*LFP;
  const float* bcn = bcI + (size_t)n*(LFP/4)*128;
  float A0 = -expf(__ldg(alog + ch*16 + 2*s));
  float A1 = -expf(__ldg(alog + ch*16 + 2*s + 1));
  float Dd = __ldg(Dv + ch);
  float* yTp = yT + (size_t)(n*DIN + ch)*LT;
  bool yl = (s == 0);
  float h0 = 0.f, h1 = 0.f;
  float yb0=0.f, yb1=0.f, yb2=0.f;

  auto step4 = [&](float4 dq, float4 uq, float4 B0q, float4 B1q,
                   float4 C0q, float4 C1q, float4 zv, int tcur, bool flushOK){
    float da[4]  = {dq.x,dq.y,dq.z,dq.w};
    float ua[4]  = {uq.x,uq.y,uq.z,uq.w};
    float B0a[4] = {B0q.x,B0q.y,B0q.z,B0q.w};
    float B1a[4] = {B1q.x,B1q.y,B1q.z,B1q.w};
    float C0a[4] = {C0q.x,C0q.y,C0q.z,C0q.w};
    float C1a[4] = {C1q.x,C1q.y,C1q.z,C1q.w};
    float za[4]  = {zv.x,zv.y,zv.z,zv.w};
    #pragma unroll
    for (int j = 0; j < 4; j++){
      float a0 = __expf(da[j]*A0);
      float a1 = __expf(da[j]*A1);
      float du = da[j]*ua[j];
      h0 = fmaf(h0, a0, du*B0a[j]);
      h1 = fmaf(h1, a1, du*B1a[j]);
      float acc = fmaf(h1, C1a[j], h0*C0a[j]);
      acc += __shfl_xor_sync(0xffffffffu, acc, 1);
      acc += __shfl_xor_sync(0xffffffffu, acc, 2);
      acc += __shfl_xor_sync(0xffffffffu, acc, 4);
      if (yl){
        float val = fmaf(ua[j], Dd, acc) * za[j];
        if (j == 0){
          if (flushOK) *(float4*)(yTp + tcur - 4) = make_float4(yb0, yb1, yb2, val);
        } else if (j == 1) yb0 = val;
        else if (j == 2)   yb1 = val;
        else               yb2 = val;
      }
    }
  };

  constexpr int NB2 = (L-1)/8;
  for (int tb = 0; tb < NB2; tb++){
    int t = tb*8;
    size_t bo0 = (size_t)(2*tb)*128, bo1 = (size_t)(2*tb+1)*128;
    float4 dqa  = __ldg((const float4*)(dtp + t));
    float4 dqb  = __ldg((const float4*)(dtp + t + 4));
    float4 uqa  = __ldg((const float4*)(xsp + t));
    float4 uqb  = __ldg((const float4*)(xsp + t + 4));
    float4 B0qa = __ldg((const float4*)(bcn + bo0 + (2*s)*4));
    float4 B1qa = __ldg((const float4*)(bcn + bo0 + (2*s+1)*4));
    float4 C0qa = __ldg((const float4*)(bcn + bo0 + 64 + (2*s)*4));
    float4 C1qa = __ldg((const float4*)(bcn + bo0 + 64 + (2*s+1)*4));
    float4 B0qb = __ldg((const float4*)(bcn + bo1 + (2*s)*4));
    float4 B1qb = __ldg((const float4*)(bcn + bo1 + (2*s+1)*4));
    float4 C0qb = __ldg((const float4*)(bcn + bo1 + (2*s)*4 + 64));
    float4 C1qb = __ldg((const float4*)(bcn + bo1 + (2*s+1)*4 + 64));
    float4 zva = make_float4(0,0,0,0), zvb = make_float4(0,0,0,0);
    if (yl){
      zva = __ldg((const float4*)(zsp + t));
      zvb = __ldg((const float4*)(zsp + t + 4));
    }
    step4(dqa, uqa, B0qa, B1qa, C0qa, C1qa, zva, t,     tb > 0);
    step4(dqb, uqb, B0qb, B1qb, C0qb, C1qb, zvb, t + 4, true);
  }
  { // tail: step t = L-1
    constexpr int t = L-1;
    constexpr size_t bo = (size_t)((L-1)/4)*128;
    float dtv = __ldg(dtp + t), u = __ldg(xsp + t);
    float B0 = __ldg(bcn + bo + (2*s)*4);
    float B1 = __ldg(bcn + bo + (2*s+1)*4);
    float C0 = __ldg(bcn + bo + 64 + (2*s)*4);
    float C1 = __ldg(bcn + bo + 64 + (2*s+1)*4);
    float a0 = __expf(dtv*A0);
    float a1 = __expf(dtv*A1);
    float du = dtv*u;
    h0 = fmaf(h0, a0, du*B0);
    h1 = fmaf(h1, a1, du*B1);
    float acc = fmaf(h1, C1, h0*C0);
    acc += __shfl_xor_sync(0xffffffffu, acc, 1);
    acc += __shfl_xor_sync(0xffffffffu, acc, 2);
    acc += __shfl_xor_sync(0xffffffffu, acc, 4);
    if (yl){
      float val = fmaf(u, Dd, acc) * __ldg(zsp + t);
      *(float4*)(yTp + L - 5) = make_float4(yb0, yb1, yb2, val);
    }
  }
}

// ============ K3b: B-run scan (16 lanes/ch, 1 state/lane, 8 tok/iter) ============
template<int L, int DIN, int LFP, int LT>
__device__ __forceinline__ void scan16u1(
  const float* __restrict__ dtT, const float* __restrict__ xsT,
  const float* __restrict__ zsT, const float* __restrict__ bcI,
  float* __restrict__ yT, const float* __restrict__ alog,
  const float* __restrict__ Dv, int n, int ch2, int lane)
{
  int half = lane >> 4, s = lane & 15;
  int ch = ch2 + half;
  const float* dtp = dtT + (size_t)(n*DIN + ch)*LFP;
  const float* xsp = xsT + (size_t)(n*DIN + ch)*LFP;
  const float* zsp = zsT + (size_t)(n*DIN + ch)*LFP;
  const float* bcn = bcI + (size_t)n*(LFP/4)*128;
  float A  = -expf(__ldg(alog + ch*16 + s));
  float Dd = __ldg(Dv + ch);
  float* yTp = yT + (size_t)(n*DIN + ch)*LT;
  bool yl = (s == 0);
  float h = 0.f;
  float yb0=0.f, yb1=0.f, yb2=0.f;

  auto step4 = [&](float4 dq, float4 uq, float4 Bq, float4 Cq,
                   float4 zv, int tcur, bool flushOK){
    float da[4] = {dq.x,dq.y,dq.z,dq.w};
    float ua[4] = {uq.x,uq.y,uq.z,uq.w};
    float Ba[4] = {Bq.x,Bq.y,Bq.z,Bq.w};
    float Ca[4] = {Cq.x,Cq.y,Cq.z,Cq.w};
    float za[4] = {zv.x,zv.y,zv.z,zv.w};
    #pragma unroll
    for (int j = 0; j < 4; j++){
      float a = __expf(da[j]*A);
      h = fmaf(h, a, da[j]*ua[j]*Ba[j]);
      float acc = h * Ca[j];
      acc += __shfl_xor_sync(0xffffffffu, acc, 1);
      acc += __shfl_xor_sync(0xffffffffu, acc, 2);
      acc += __shfl_xor_sync(0xffffffffu, acc, 4);
      acc += __shfl_xor_sync(0xffffffffu, acc, 8);
      if (yl){
        float val = fmaf(ua[j], Dd, acc) * za[j];
        if (j == 0){
          if (flushOK) *(float4*)(yTp + tcur - 4) = make_float4(yb0, yb1, yb2, val);
        } else if (j == 1) yb0 = val;
        else if (j == 2)   yb1 = val;
        else               yb2 = val;
      }
    }
  };

  constexpr int NB2 = (L-1)/8;
  for (int tb = 0; tb < NB2; tb++){
    int t = tb*8;
    size_t bo0 = (size_t)(2*tb)*128, bo1 = (size_t)(2*tb+1)*128;
    float4 dqa = __ldg((const float4*)(dtp + t));
    float4 dqb = __ldg((const float4*)(dtp + t + 4));
    float4 uqa = __ldg((const float4*)(xsp + t));
    float4 uqb = __ldg((const float4*)(xsp + t + 4));
    float4 Bqa = __ldg((const float4*)(bcn + bo0 + s*4));
    float4 Cqa = __ldg((const float4*)(bcn + bo0 + 64 + s*4));
    float4 Bqb = __ldg((const float4*)(bcn + bo1 + s*4));
    float4 Cqb = __ldg((const float4*)(bcn + bo1 + 64 + s*4));
    float4 zva = make_float4(0,0,0,0), zvb = make_float4(0,0,0,0);
    if (yl){
      zva = __ldg((const float4*)(zsp + t));
      zvb = __ldg((const float4*)(zsp + t + 4));
    }
    step4(dqa, uqa, Bqa, Cqa, zva, t,     tb > 0);
    step4(dqb, uqb, Bqb, Cqb, zvb, t + 4, true);
  }
  { // tail: step t = L-1
    constexpr int t = L-1;
    constexpr size_t bo = (size_t)((L-1)/4)*128;
    float dtv = __ldg(dtp + t), u = __ldg(xsp + t);
    float Bv = __ldg(bcn + bo + s*4);
    float Cv = __ldg(bcn + bo + 64 + s*4);
    float a = __expf(dtv*A);
    h = fmaf(h, a, dtv*u*Bv);
    float acc = h * Cv;
    acc += __shfl_xor_sync(0xffffffffu, acc, 1);
    acc += __shfl_xor_sync(0xffffffffu, acc, 2);
    acc += __shfl_xor_sync(0xffffffffu, acc, 4);
    acc += __shfl_xor_sync(0xffffffffu, acc, 8);
    if (yl){
      float val = fmaf(u, Dd, acc) * __ldg(zsp + t);
      *(float4*)(yTp + L - 5) = make_float4(yb0, yb1, yb2, val);
    }
  }
}

// Block order: long B chains first (blocks 0..767), short A chains last.
__global__ void __launch_bounds__(128) k_scan(
  const float* __restrict__ alogA, const float* __restrict__ DA,
  const float* __restrict__ alogB, const float* __restrict__ DB)
{
  int wg = blockIdx.x*4 + (threadIdx.x >> 5);     // 0..4095
  int lane = threadIdx.x & 31;
  if (wg < 1536){                                  // B run 0: 24 warps/seq, 2 ch/warp
    int n = wg/24, ch2 = (wg - n*24)*2;
    scan16u1<LB,48,LPB,LTB>(gB_dtT0, gB_xsT0, gB_zsT0, gB_bcI0, gB_yT0, alogB, DB, n, ch2, lane);
  } else if (wg < 3072){                           // B run 1
    int w2 = wg - 1536;
    int n = w2/24, ch2 = (w2 - n*24)*2;
    scan16u1<LB,48,LPB,LTB>(gB_dtT1, gB_xsT1, gB_zsT1, gB_bcI1, gB_yT1, alogB, DB, n, ch2, lane);
  } else {                                         // A run: 16 warps/seq, 4 ch/warp
    int w3 = wg - 3072;
    int n = w3 >> 4, ch4 = (w3 & 15)*4;
    scan8u2<LA,64,LPA,LTA>(gA_dtT, gA_xsT, gA_zsT, gA_bcI, gA_yT, alogA, DA, n, ch4, lane);
  }
}

// ============ K4: out_proj (transposed y via smem tile, FFMA2) ============
template<int RUN>
__global__ void __launch_bounds__(256) k_outproj(const float* __restrict__ Wo)
{
  constexpr int DIN = (RUN==0)?64:48;
  constexpr int DM  = (RUN==0)?32:24;
  constexpr int LT  = (RUN==0)?LTA:LTB;
  const float* yT = bufYT<RUN>();
  float* o = bufO<RUN>();
  __shared__ float Wt[DIN*32];
  __shared__ __align__(16) float y_s[DIN][34];
  int tid = threadIdx.x;
  for (int i = tid; i < DIN*32; i += 256){
    int d = i >> 5, oo = i & 31;
    Wt[i] = (oo < DM) ? Wo[oo*DIN + d] : 0.f;
  }
  int w = tid >> 5, lane = tid & 31;
  int n = blockIdx.y;
  int tile0 = blockIdx.x*32;
  for (int i = tid; i < DIN*8; i += 256){
    int ch = i >> 3, v = i & 7;
    float4 yv = *(const float4*)(yT + (size_t)(n*DIN + ch)*LT + tile0 + 4*v);
    y_s[ch][4*v+0] = yv.x; y_s[ch][4*v+1] = yv.y;
    y_s[ch][4*v+2] = yv.z; y_s[ch][4*v+3] = yv.w;
  }
  __syncthreads();
  unsigned long long ap0=0ull, ap1=0ull;
  #pragma unroll 8
  for (int d = 0; d < DIN; d++){
    const unsigned long long* yp2 = (const unsigned long long*)&y_s[d][w*4];
    unsigned long long y01 = yp2[0], y23 = yp2[1];
    float wv = Wt[d*32 + lane];
    unsigned long long wp = pack2(wv, wv);
    ffma2(ap0, wp, y01);
    ffma2(ap1, wp, y23);
  }
  float2 u0 = unpack2(ap0), u1 = unpack2(ap1);
  float acc[4] = {u0.x, u0.y, u1.x, u1.y};
  if (lane < DM){
    #pragma unroll
    for (int tok = 0; tok < 4; tok++){
      int t = tile0 + w*4 + tok;
      o[(size_t)(n*LT + t)*DM + lane] = acc[tok];
    }
  }
}

// ============ K5: combine into output ============
__global__ void __launch_bounds__(256) k_combine(float* __restrict__ out)
{
  int idx = blockIdx.x*256 + threadIdx.x;
  if (idx >= 128*192*192) return;
  int c = idx / 36864;
  int rem = idx - c*36864;
  int n = rem / 576;
  int rem2 = rem - n*576;
  int i = rem2 / 24;
  int j = rem2 - i*24;
  int d = c >> 2, r1 = (c >> 1) & 1, r2 = c & 1;
  float v0 = gA_o [(size_t)(n*2304 + (2*i+r1)*48 + 2*j + r2)*32 + d];
  float v1 = gB_o0[(size_t)(n*3072 + c*24 + j)*24 + i];
  float v2 = gB_o1[(size_t)(n*3072 + c*24 + i)*24 + j];
  out[idx] = (v0 + v1 + v2) * (1.f/3.f);
}

// ============ host launch ============
extern "C" void kernel_launch(void* const* d_in, const int* in_sizes, int n_in,
                              void* d_out, int out_size) {
  (void)in_sizes; (void)n_in; (void)out_size;
  const float* X   = (const float*)d_in[0];
  const float* NW  = (const float*)d_in[1];
  const float* NB  = (const float*)d_in[2];
  const float* N2W = (const float*)d_in[3];
  const float* N2B = (const float*)d_in[4];
  const float* GT1 = (const float*)d_in[5];
  const float* GT2 = (const float*)d_in[6];
  const float* M1_IN  = (const float*)d_in[7];
  const float* M1_CW  = (const float*)d_in[8];
  const float* M1_CB  = (const float*)d_in[9];
  const float* M1_XW  = (const float*)d_in[10];
  const float* M1_DTW = (const float*)d_in[11];
  const float* M1_DTB = (const float*)d_in[12];
  const float* M1_AL  = (const float*)d_in[13];
  const float* M1_D   = (const float*)d_in[14];
  const float* M1_OW  = (const float*)d_in[15];
  const float* M2_IN  = (const float*)d_in[16];
  const float* M2_CW  = (const float*)d_in[17];
  const float* M2_CB  = (const float*)d_in[18];
  const float* M2_XW  = (const float*)d_in[19];
  const float* M2_DTW = (const float*)d_in[20];
  const float* M2_DTB = (const float*)d_in[21];
  const float* M2_AL  = (const float*)d_in[22];
  const float* M2_D   = (const float*)d_in[23];
  const float* M2_OW  = (const float*)d_in[24];

  k_inproj<0><<<dim3(73, 64), 128>>>(X, NW,  NB,  GT1, M1_IN);
  k_inproj<1><<<dim3(97, 64), 128>>>(X, N2W, N2B, GT2, M2_IN);
  k_inproj<2><<<dim3(97, 64), 128>>>(X, N2W, N2B, GT2, M2_IN);

  k_convxp<0><<<dim3(73, 64), 256>>>(M1_CW, M1_CB, M1_XW, M1_DTW, M1_DTB);
  k_convxp<1><<<dim3(97, 64), 256>>>(M2_CW, M2_CB, M2_XW, M2_DTW, M2_DTB);
  k_convxp<2><<<dim3(97, 64), 256>>>(M2_CW, M2_CB, M2_XW, M2_DTW, M2_DTB);

  k_scan<<<1024, 128>>>(M1_AL, M1_D, M2_AL, M2_D);

  k_outproj<0><<<dim3(72, 64), 256>>>(M1_OW);
  k_outproj<1><<<dim3(96, 64), 256>>>(M2_OW);
  k_outproj<2><<<dim3(96, 64), 256>>>(M2_OW);

  k_combine<<<18432, 256>>>((float*)d_out);
}

// round 15
// speedup vs baseline: 1.1020x; 1.1020x over previous
#include <cuda_runtime.h>
#include <math.h>

#define NSEQ 64
static constexpr int LA  = 2305;   // run0 length (1 gt + 48*48)
static constexpr int LB  = 3073;   // run1/2 length (1 gt + 128*24)
static constexpr int LPA = 2336;   // padded strides (mult of 32)
static constexpr int LPB = 3104;
static constexpr int LTA = 2304;   // output token counts (mult of 32)
static constexpr int LTB = 3072;

// ---------- scratch (device globals; allocation-free) ----------
__device__ __align__(16) float gA_xz [NSEQ*LA*128];
__device__ __align__(16) float gA_dtT[NSEQ*64*LPA];
__device__ __align__(16) float gA_xsT[NSEQ*64*LPA];
__device__ __align__(16) float gA_zsT[NSEQ*64*LPA];
__device__ __align__(16) float gA_bcI[NSEQ*32*LPA];   // [n][tb][comp32][4]
__device__ __align__(16) float gA_yT [NSEQ*64*LTA];   // [n][ch][t]
__device__ __align__(16) float gA_o  [NSEQ*LTA*32];

__device__ __align__(16) float gB_xz0 [NSEQ*LB*96];
__device__ __align__(16) float gB_dtT0[NSEQ*48*LPB];
__device__ __align__(16) float gB_xsT0[NSEQ*48*LPB];
__device__ __align__(16) float gB_zsT0[NSEQ*48*LPB];
__device__ __align__(16) float gB_bcI0[NSEQ*32*LPB];
__device__ __align__(16) float gB_yT0 [NSEQ*48*LTB];
__device__ __align__(16) float gB_o0  [NSEQ*LTB*24];

__device__ __align__(16) float gB_xz1 [NSEQ*LB*96];
__device__ __align__(16) float gB_dtT1[NSEQ*48*LPB];
__device__ __align__(16) float gB_xsT1[NSEQ*48*LPB];
__device__ __align__(16) float gB_zsT1[NSEQ*48*LPB];
__device__ __align__(16) float gB_bcI1[NSEQ*32*LPB];
__device__ __align__(16) float gB_yT1 [NSEQ*48*LTB];
__device__ __align__(16) float gB_o1  [NSEQ*LTB*24];

template<int RUN> __device__ __forceinline__ float* bufXZ(){
  if constexpr (RUN==0) return gA_xz; else if constexpr (RUN==1) return gB_xz0; else return gB_xz1; }
template<int RUN> __device__ __forceinline__ float* bufDTT(){
  if constexpr (RUN==0) return gA_dtT; else if constexpr (RUN==1) return gB_dtT0; else return gB_dtT1; }
template<int RUN> __device__ __forceinline__ float* bufXST(){
  if constexpr (RUN==0) return gA_xsT; else if constexpr (RUN==1) return gB_xsT0; else return gB_xsT1; }
template<int RUN> __device__ __forceinline__ float* bufZST(){
  if constexpr (RUN==0) return gA_zsT; else if constexpr (RUN==1) return gB_zsT0; else return gB_zsT1; }
template<int RUN> __device__ __forceinline__ float* bufBCI(){
  if constexpr (RUN==0) return gA_bcI; else if constexpr (RUN==1) return gB_bcI0; else return gB_bcI1; }
template<int RUN> __device__ __forceinline__ float* bufYT(){
  if constexpr (RUN==0) return gA_yT; else if constexpr (RUN==1) return gB_yT0; else return gB_yT1; }
template<int RUN> __device__ __forceinline__ float* bufO(){
  if constexpr (RUN==0) return gA_o; else if constexpr (RUN==1) return gB_o0; else return gB_o1; }

__device__ __forceinline__ float warp_sum(float v){
  v += __shfl_xor_sync(0xffffffffu, v, 16);
  v += __shfl_xor_sync(0xffffffffu, v, 8);
  v += __shfl_xor_sync(0xffffffffu, v, 4);
  v += __shfl_xor_sync(0xffffffffu, v, 2);
  v += __shfl_xor_sync(0xffffffffu, v, 1);
  return v;
}
__device__ __forceinline__ float silu_f(float x){
  return __fdividef(x, 1.f + __expf(-x));
}

// ---------- packed f32x2 helpers ----------
__device__ __forceinline__ unsigned long long pack2(float lo, float hi){
  unsigned long long r;
  asm("mov.b64 %0, {%1, %2};" : "=l"(r) : "f"(lo), "f"(hi));
  return r;
}
__device__ __forceinline__ float2 unpack2(unsigned long long v){
  float2 f;
  asm("mov.b64 {%0, %1}, %2;" : "=f"(f.x), "=f"(f.y) : "l"(v));
  return f;
}
__device__ __forceinline__ void ffma2(unsigned long long &d, unsigned long long a, unsigned long long b){
  asm("fma.rn.f32x2 %0, %1, %2, %0;" : "+l"(d) : "l"(a), "l"(b));
}

// ============ K1: gather + layernorm + in_proj (FFMA2) ============
template<int RUN>
__global__ void __launch_bounds__(128) k_inproj(
    const float* __restrict__ x, const float* __restrict__ nw,
    const float* __restrict__ nb, const float* __restrict__ gt,
    const float* __restrict__ Win)
{
  constexpr int DM  = (RUN==0)?32:24;
  constexpr int DXZ = (RUN==0)?128:96;
  constexpr int LF  = (RUN==0)?LA:LB;
  constexpr int KO  = DXZ/32;
  __shared__ float Wtr[DM*128];                   // [d][lane][4] (k padded to 4)
  __shared__ __align__(16) float vsh[4][DM][8];

  int tid = threadIdx.x;
  for (int i = tid; i < DM*128; i += 128){
    int d = i >> 7, r = i & 127, ln = r >> 2, k = r & 3;
    Wtr[i] = (k < KO) ? Win[(k*32+ln)*DM + d] : 0.f;
  }
  int w = tid >> 5, lane = tid & 31;
  int n = blockIdx.y, bh = n >> 3, bw = n & 7;
  int t0 = (blockIdx.x*4 + w)*8;

  float v[8];
  #pragma unroll
  for (int tok = 0; tok < 8; tok++){
    int t = t0 + tok; float val = 0.f;
    if (lane < DM && t < LF){
      if (t == 0) val = gt[lane];
      else {
        int q = t - 1, addr;
        if (RUN == 0){
          int row = q / 48, col = q - row*48;
          int i0 = row >> 1, r1 = row & 1, j0 = col >> 1, r2 = col & 1;
          addr = (lane*4 + r1*2 + r2)*36864 + (bh*24 + i0)*192 + bw*24 + j0;
        } else if (RUN == 1){
          int c = q / 24, p = q - c*24;
          addr = c*36864 + (bh*24 + lane)*192 + bw*24 + p;
        } else {
          int c = q / 24, p = q - c*24;
          addr = c*36864 + (bh*24 + p)*192 + bw*24 + lane;
        }
        val = __ldg(x + addr);
      }
    }
    v[tok] = val;
  }
  float nwv = (lane < DM) ? nw[lane] : 0.f;
  float nbv = (lane < DM) ? nb[lane] : 0.f;
  #pragma unroll
  for (int tok = 0; tok < 8; tok++){
    float s  = warp_sum(v[tok]);
    float s2 = warp_sum(v[tok]*v[tok]);
    float m  = s * (1.f/DM);
    float var = s2 * (1.f/DM) - m*m;
    float vn = (v[tok] - m) * rsqrtf(var + 1e-5f) * nwv + nbv;
    if (lane < DM) vsh[w][lane][tok] = vn;
  }
  __syncthreads();

  unsigned long long accp[KO][4];
  #pragma unroll
  for (int k = 0; k < KO; k++)
    #pragma unroll
    for (int p = 0; p < 4; p++) accp[k][p] = 0ull;

  #pragma unroll 4
  for (int d = 0; d < DM; d++){
    const ulonglong2* vp = (const ulonglong2*)vsh[w][d];
    ulonglong2 va = vp[0], vb = vp[1];
    float4 wq = *(const float4*)&Wtr[(d*32+lane)*4];
    float wa[4] = {wq.x, wq.y, wq.z, wq.w};
    #pragma unroll
    for (int k = 0; k < KO; k++){
      unsigned long long wp = pack2(wa[k], wa[k]);
      ffma2(accp[k][0], wp, va.x);
      ffma2(accp[k][1], wp, va.y);
      ffma2(accp[k][2], wp, vb.x);
      ffma2(accp[k][3], wp, vb.y);
    }
  }
  float* xz = bufXZ<RUN>();
  #pragma unroll
  for (int p = 0; p < 4; p++){
    float2 f[KO];
    #pragma unroll
    for (int k = 0; k < KO; k++) f[k] = unpack2(accp[k][p]);
    #pragma unroll
    for (int e = 0; e < 2; e++){
      int t = t0 + 2*p + e;
      if (t < LF){
        float* op = xz + (n*LF + t)*DXZ + lane;
        #pragma unroll
        for (int k = 0; k < KO; k++) op[32*k] = e ? f[k].y : f[k].x;
      }
    }
  }
}

// ============ K2: conv + silu + x_proj + dt (FFMA2 xproj) ============
template<int RUN>
__global__ void __launch_bounds__(256) k_convxp(
  const float* __restrict__ convw, const float* __restrict__ convb,
  const float* __restrict__ Wx,    const float* __restrict__ dtw,
  const float* __restrict__ dtb)
{
  constexpr int DIN = (RUN==0)?64:48;
  constexpr int DXZ = 2*DIN;
  constexpr int LF  = (RUN==0)?LA:LB;
  constexpr int LFP = (RUN==0)?LPA:LPB;
  const float* xz = bufXZ<RUN>();
  float* xsT = bufXST<RUN>();
  float* zsT = bufZST<RUN>();
  float* dtT = bufDTT<RUN>();
  float* bcI = bufBCI<RUN>();

  __shared__ float Wxt[DIN*34];          // [d][o]
  __shared__ __align__(16) float xs_s[DIN][34];
  __shared__ __align__(16) float zs_s[DIN][34];
  __shared__ __align__(16) float dt_s[DIN][34];
  __shared__ float bc_s[32][33];

  int tid = threadIdx.x;
  for (int i = tid; i < 34*DIN; i += 256){
    int o = i / DIN, d = i - o*DIN;
    Wxt[d*34 + o] = Wx[i];
  }
  int w = tid >> 5, lane = tid & 31;
  int n = blockIdx.y;
  int tile0 = blockIdx.x*32;
  int t0 = tile0 + w*4;

  float cw[2][4], cb[2], w0c[2], w1c[2], db[2];
  #pragma unroll
  for (int kk = 0; kk < 2; kk++){
    int ch = lane + 32*kk;
    bool ok = ch < DIN;
    #pragma unroll
    for (int k = 0; k < 4; k++) cw[kk][k] = ok ? convw[ch*4+k] : 0.f;
    cb[kk]  = ok ? convb[ch]   : 0.f;
    w0c[kk] = ok ? dtw[ch*2+0] : 0.f;
    w1c[kk] = ok ? dtw[ch*2+1] : 0.f;
    db[kk]  = ok ? dtb[ch]     : 0.f;
  }
  #pragma unroll
  for (int tok = 0; tok < 4; tok++){
    int t = t0 + tok;
    bool valid = t < LF;
    #pragma unroll
    for (int kk = 0; kk < 2; kk++){
      int ch = lane + 32*kk;
      if (ch < DIN){
        float a = cb[kk];
        float zval = 0.f;
        if (valid){
          #pragma unroll
          for (int k = 0; k < 4; k++){
            int ts = t + k - 3;
            if (ts >= 0) a = fmaf(xz[(n*LF + ts)*DXZ + ch], cw[kk][k], a);
          }
          zval = xz[(n*LF + t)*DXZ + DIN + ch];
        }
        xs_s[ch][w*4+tok] = silu_f(a);
        zs_s[ch][w*4+tok] = silu_f(zval);
      }
    }
  }
  __syncthreads();   // Wxt + xs_s ready

  unsigned long long ap0=0ull, ap1=0ull, a2p0=0ull, a2p1=0ull;
  #pragma unroll 8
  for (int d = 0; d < DIN; d++){
    const unsigned long long* xp = (const unsigned long long*)&xs_s[d][w*4];
    unsigned long long x01 = xp[0], x23 = xp[1];
    float wv = Wxt[d*34 + lane];
    unsigned long long wp = pack2(wv, wv);
    ffma2(ap0, wp, x01);
    ffma2(ap1, wp, x23);
    if (lane < 2){
      float w2 = Wxt[d*34 + 32 + lane];
      unsigned long long wp2 = pack2(w2, w2);
      ffma2(a2p0, wp2, x01);
      ffma2(a2p1, wp2, x23);
    }
  }
  float2 u0 = unpack2(ap0), u1 = unpack2(ap1);
  float acc[4]  = {u0.x, u0.y, u1.x, u1.y};
  float2 q0 = unpack2(a2p0), q1 = unpack2(a2p1);
  float acc2[4] = {q0.x, q0.y, q1.x, q1.y};

  #pragma unroll
  for (int tok = 0; tok < 4; tok++){
    float d0 = __shfl_sync(0xffffffffu, acc[tok], 0);
    float d1 = __shfl_sync(0xffffffffu, acc[tok], 1);
    #pragma unroll
    for (int kk = 0; kk < 2; kk++){
      int ch = lane + 32*kk;
      if (ch < DIN){
        float r = fmaf(w0c[kk], d0, fmaf(w1c[kk], d1, db[kk]));
        dt_s[ch][w*4+tok] = fmaxf(r, 0.f) + __logf(1.f + __expf(-fabsf(r)));
      }
    }
    if (lane >= 2) bc_s[lane-2][w*4+tok]  = acc[tok];
    else           bc_s[30+lane][w*4+tok] = acc2[tok];
  }
  __syncthreads();

  // coalesced flush: consecutive threads -> consecutive float4 along t
  for (int i = tid; i < DIN*8; i += 256){
    int ch = i >> 3, v = i & 7;
    int tt = tile0 + 4*v;
    size_t off = (size_t)(n*DIN + ch)*LFP + tt;
    *(float4*)(xsT + off) = make_float4(xs_s[ch][4*v],xs_s[ch][4*v+1],xs_s[ch][4*v+2],xs_s[ch][4*v+3]);
    *(float4*)(zsT + off) = make_float4(zs_s[ch][4*v],zs_s[ch][4*v+1],zs_s[ch][4*v+2],zs_s[ch][4*v+3]);
    *(float4*)(dtT + off) = make_float4(dt_s[ch][4*v],dt_s[ch][4*v+1],dt_s[ch][4*v+2],dt_s[ch][4*v+3]);
  }
  // bc interleaved flush: [n][tb][comp][4]
  {
    int tbl = tid >> 5, comp = tid & 31;
    float4 bv = make_float4(bc_s[comp][4*tbl],bc_s[comp][4*tbl+1],bc_s[comp][4*tbl+2],bc_s[comp][4*tbl+3]);
    *(float4*)(bcI + ((size_t)(n*(LFP/4) + tile0/4 + tbl)*32 + comp)*4) = bv;
  }
}

// ============ K3: selective scan (8 lanes/ch, 2 states/lane, 8 tok/iter) ============
template<int L, int DIN, int LFP, int LT>
__device__ __forceinline__ void scan8u2(
  const float* __restrict__ dtT, const float* __restrict__ xsT,
  const float* __restrict__ zsT, const float* __restrict__ bcI,
  float* __restrict__ yT, const float* __restrict__ alog,
  const float* __restrict__ Dv, int n, int ch4, int lane)
{
  int g = lane >> 3, s = lane & 7;
  int ch = ch4 + g;
  const float* dtp = dtT + (size_t)(n*DIN + ch)*LFP;
  const float* xsp = xsT + (size_t)(n*DIN + ch)*LFP;
  const float* zsp = zsT + (size_t)(n*DIN + ch)*LFP;
  const float* bcn = bcI + (size_t)n*(LFP/4)*128;
  float A0 = -expf(__ldg(alog + ch*16 + 2*s));
  float A1 = -expf(__ldg(alog + ch*16 + 2*s + 1));
  float Dd = __ldg(Dv + ch);
  float* yTp = yT + (size_t)(n*DIN + ch)*LT;
  bool yl = (s == 0);
  float h0 = 0.f, h1 = 0.f;
  float yb0=0.f, yb1=0.f, yb2=0.f;

  auto step4 = [&](float4 dq, float4 uq, float4 B0q, float4 B1q,
                   float4 C0q, float4 C1q, float4 zv, int tcur, bool flushOK){
    float da[4]  = {dq.x,dq.y,dq.z,dq.w};
    float ua[4]  = {uq.x,uq.y,uq.z,uq.w};
    float B0a[4] = {B0q.x,B0q.y,B0q.z,B0q.w};
    float B1a[4] = {B1q.x,B1q.y,B1q.z,B1q.w};
    float C0a[4] = {C0q.x,C0q.y,C0q.z,C0q.w};
    float C1a[4] = {C1q.x,C1q.y,C1q.z,C1q.w};
    float za[4]  = {zv.x,zv.y,zv.z,zv.w};
    #pragma unroll
    for (int j = 0; j < 4; j++){
      float a0 = __expf(da[j]*A0);
      float a1 = __expf(da[j]*A1);
      float du = da[j]*ua[j];
      h0 = fmaf(h0, a0, du*B0a[j]);
      h1 = fmaf(h1, a1, du*B1a[j]);
      float acc = fmaf(h1, C1a[j], h0*C0a[j]);
      acc += __shfl_xor_sync(0xffffffffu, acc, 1);
      acc += __shfl_xor_sync(0xffffffffu, acc, 2);
      acc += __shfl_xor_sync(0xffffffffu, acc, 4);
      if (yl){
        float val = fmaf(ua[j], Dd, acc) * za[j];
        if (j == 0){
          if (flushOK) *(float4*)(yTp + tcur - 4) = make_float4(yb0, yb1, yb2, val);
        } else if (j == 1) yb0 = val;
        else if (j == 2)   yb1 = val;
        else               yb2 = val;
      }
    }
  };

  constexpr int NB2 = (L-1)/8;
  for (int tb = 0; tb < NB2; tb++){
    int t = tb*8;
    size_t bo0 = (size_t)(2*tb)*128, bo1 = (size_t)(2*tb+1)*128;
    float4 dqa  = __ldg((const float4*)(dtp + t));
    float4 dqb  = __ldg((const float4*)(dtp + t + 4));
    float4 uqa  = __ldg((const float4*)(xsp + t));
    float4 uqb  = __ldg((const float4*)(xsp + t + 4));
    float4 B0qa = __ldg((const float4*)(bcn + bo0 + (2*s)*4));
    float4 B1qa = __ldg((const float4*)(bcn + bo0 + (2*s+1)*4));
    float4 C0qa = __ldg((const float4*)(bcn + bo0 + 64 + (2*s)*4));
    float4 C1qa = __ldg((const float4*)(bcn + bo0 + 64 + (2*s+1)*4));
    float4 B0qb = __ldg((const float4*)(bcn + bo1 + (2*s)*4));
    float4 B1qb = __ldg((const float4*)(bcn + bo1 + (2*s+1)*4));
    float4 C0qb = __ldg((const float4*)(bcn + bo1 + (2*s)*4 + 64));
    float4 C1qb = __ldg((const float4*)(bcn + bo1 + (2*s+1)*4 + 64));
    float4 zva = make_float4(0,0,0,0), zvb = make_float4(0,0,0,0);
    if (yl){
      zva = __ldg((const float4*)(zsp + t));
      zvb = __ldg((const float4*)(zsp + t + 4));
    }
    step4(dqa, uqa, B0qa, B1qa, C0qa, C1qa, zva, t,     tb > 0);
    step4(dqb, uqb, B0qb, B1qb, C0qb, C1qb, zvb, t + 4, true);
  }
  { // tail: step t = L-1
    constexpr int t = L-1;
    constexpr size_t bo = (size_t)((L-1)/4)*128;
    float dtv = __ldg(dtp + t), u = __ldg(xsp + t);
    float B0 = __ldg(bcn + bo + (2*s)*4);
    float B1 = __ldg(bcn + bo + (2*s+1)*4);
    float C0 = __ldg(bcn + bo + 64 + (2*s)*4);
    float C1 = __ldg(bcn + bo + 64 + (2*s+1)*4);
    float a0 = __expf(dtv*A0);
    float a1 = __expf(dtv*A1);
    float du = dtv*u;
    h0 = fmaf(h0, a0, du*B0);
    h1 = fmaf(h1, a1, du*B1);
    float acc = fmaf(h1, C1, h0*C0);
    acc += __shfl_xor_sync(0xffffffffu, acc, 1);
    acc += __shfl_xor_sync(0xffffffffu, acc, 2);
    acc += __shfl_xor_sync(0xffffffffu, acc, 4);
    if (yl){
      float val = fmaf(u, Dd, acc) * __ldg(zsp + t);
      *(float4*)(yTp + L - 5) = make_float4(yb0, yb1, yb2, val);
    }
  }
}

__global__ void __launch_bounds__(128) k_scan(
  const float* __restrict__ alogA, const float* __restrict__ DA,
  const float* __restrict__ alogB, const float* __restrict__ DB)
{
  int wg = (blockIdx.x*128 + threadIdx.x) >> 5;   // 0..2559
  int lane = threadIdx.x & 31;
  if (wg < 1024){
    int n = wg >> 4, ch4 = (wg & 15)*4;           // 16 warps/seq, 4 ch/warp
    scan8u2<LA,64,LPA,LTA>(gA_dtT, gA_xsT, gA_zsT, gA_bcI, gA_yT, alogA, DA, n, ch4, lane);
  } else {
    int w2 = wg - 1024;                           // 0..1535
    if (w2 < 768){
      int n = w2/12, ch4 = (w2 - n*12)*4;         // 12 warps/seq, 4 ch/warp
      scan8u2<LB,48,LPB,LTB>(gB_dtT0, gB_xsT0, gB_zsT0, gB_bcI0, gB_yT0, alogB, DB, n, ch4, lane);
    } else {
      w2 -= 768;
      int n = w2/12, ch4 = (w2 - n*12)*4;
      scan8u2<LB,48,LPB,LTB>(gB_dtT1, gB_xsT1, gB_zsT1, gB_bcI1, gB_yT1, alogB, DB, n, ch4, lane);
    }
  }
}

// ============ K4: out_proj (transposed y via smem tile, FFMA2) ============
template<int RUN>
__global__ void __launch_bounds__(256) k_outproj(const float* __restrict__ Wo)
{
  constexpr int DIN = (RUN==0)?64:48;
  constexpr int DM  = (RUN==0)?32:24;
  constexpr int LT  = (RUN==0)?LTA:LTB;
  const float* yT = bufYT<RUN>();
  float* o = bufO<RUN>();
  __shared__ float Wt[DIN*32];
  __shared__ __align__(16) float y_s[DIN][34];
  int tid = threadIdx.x;
  for (int i = tid; i < DIN*32; i += 256){
    int d = i >> 5, oo = i & 31;
    Wt[i] = (oo < DM) ? Wo[oo*DIN + d] : 0.f;
  }
  int w = tid >> 5, lane = tid & 31;
  int n = blockIdx.y;
  int tile0 = blockIdx.x*32;
  for (int i = tid; i < DIN*8; i += 256){
    int ch = i >> 3, v = i & 7;
    float4 yv = *(const float4*)(yT + (size_t)(n*DIN + ch)*LT + tile0 + 4*v);
    y_s[ch][4*v+0] = yv.x; y_s[ch][4*v+1] = yv.y;
    y_s[ch][4*v+2] = yv.z; y_s[ch][4*v+3] = yv.w;
  }
  __syncthreads();
  unsigned long long ap0=0ull, ap1=0ull;
  #pragma unroll 8
  for (int d = 0; d < DIN; d++){
    const unsigned long long* yp2 = (const unsigned long long*)&y_s[d][w*4];
    unsigned long long y01 = yp2[0], y23 = yp2[1];
    float wv = Wt[d*32 + lane];
    unsigned long long wp = pack2(wv, wv);
    ffma2(ap0, wp, y01);
    ffma2(ap1, wp, y23);
  }
  float2 u0 = unpack2(ap0), u1 = unpack2(ap1);
  float acc[4] = {u0.x, u0.y, u1.x, u1.y};
  if (lane < DM){
    #pragma unroll
    for (int tok = 0; tok < 4; tok++){
      int t = tile0 + w*4 + tok;
      o[(size_t)(n*LT + t)*DM + lane] = acc[tok];
    }
  }
}

// ============ K5: combine into output (4 outputs/thread, STG.128) ============
__global__ void __launch_bounds__(256) k_combine(float* __restrict__ out)
{
  int base = (blockIdx.x*256 + threadIdx.x)*4;
  if (base >= 128*192*192) return;
  float r[4];
  #pragma unroll
  for (int e = 0; e < 4; e++){
    int idx = base + e;
    int c = idx / 36864;
    int rem = idx - c*36864;
    int n = rem / 576;
    int rem2 = rem - n*576;
    int i = rem2 / 24;
    int j = rem2 - i*24;
    int d = c >> 2, r1 = (c >> 1) & 1, r2 = c & 1;
    float v0 = __ldg(&gA_o [(size_t)(n*2304 + (2*i+r1)*48 + 2*j + r2)*32 + d]);
    float v1 = __ldg(&gB_o0[(size_t)(n*3072 + c*24 + j)*24 + i]);
    float v2 = __ldg(&gB_o1[(size_t)(n*3072 + c*24 + i)*24 + j]);
    r[e] = (v0 + v1 + v2) * (1.f/3.f);
  }
  *(float4*)(out + base) = make_float4(r[0], r[1], r[2], r[3]);
}

// ============ host launch ============
extern "C" void kernel_launch(void* const* d_in, const int* in_sizes, int n_in,
                              void* d_out, int out_size) {
  (void)in_sizes; (void)n_in; (void)out_size;
  const float* X   = (const float*)d_in[0];
  const float* NW  = (const float*)d_in[1];
  const float* NB  = (const float*)d_in[2];
  const float* N2W = (const float*)d_in[3];
  const float* N2B = (const float*)d_in[4];
  const float* GT1 = (const float*)d_in[5];
  const float* GT2 = (const float*)d_in[6];
  const float* M1_IN  = (const float*)d_in[7];
  const float* M1_CW  = (const float*)d_in[8];
  const float* M1_CB  = (const float*)d_in[9];
  const float* M1_XW  = (const float*)d_in[10];
  const float* M1_DTW = (const float*)d_in[11];
  const float* M1_DTB = (const float*)d_in[12];
  const float* M1_AL  = (const float*)d_in[13];
  const float* M1_D   = (const float*)d_in[14];
  const float* M1_OW  = (const float*)d_in[15];
  const float* M2_IN  = (const float*)d_in[16];
  const float* M2_CW  = (const float*)d_in[17];
  const float* M2_CB  = (const float*)d_in[18];
  const float* M2_XW  = (const float*)d_in[19];
  const float* M2_DTW = (const float*)d_in[20];
  const float* M2_DTB = (const float*)d_in[21];
  const float* M2_AL  = (const float*)d_in[22];
  const float* M2_D   = (const float*)d_in[23];
  const float* M2_OW  = (const float*)d_in[24];

  k_inproj<0><<<dim3(73, 64), 128>>>(X, NW,  NB,  GT1, M1_IN);
  k_inproj<1><<<dim3(97, 64), 128>>>(X, N2W, N2B, GT2, M2_IN);
  k_inproj<2><<<dim3(97, 64), 128>>>(X, N2W, N2B, GT2, M2_IN);

  k_convxp<0><<<dim3(73, 64), 256>>>(M1_CW, M1_CB, M1_XW, M1_DTW, M1_DTB);
  k_convxp<1><<<dim3(97, 64), 256>>>(M2_CW, M2_CB, M2_XW, M2_DTW, M2_DTB);
  k_convxp<2><<<dim3(97, 64), 256>>>(M2_CW, M2_CB, M2_XW, M2_DTW, M2_DTB);

  k_scan<<<640, 128>>>(M1_AL, M1_D, M2_AL, M2_D);

  k_outproj<0><<<dim3(72, 64), 256>>>(M1_OW);
  k_outproj<1><<<dim3(96, 64), 256>>>(M2_OW);
  k_outproj<2><<<dim3(96, 64), 256>>>(M2_OW);

  k_combine<<<4608, 256>>>((float*)d_out);
}

// round 17
// speedup vs baseline: 1.2203x; 1.1073x over previous
#include <cuda_runtime.h>
#include <math.h>

#define NSEQ 64
static constexpr int LA  = 2305;   // run0 length (1 gt + 48*48)
static constexpr int LB  = 3073;   // run1/2 length (1 gt + 128*24)
static constexpr int LPA = 2336;   // padded strides (mult of 32)
static constexpr int LPB = 3104;
static constexpr int LTA = 2304;   // output token counts (mult of 32)
static constexpr int LTB = 3072;

// ---------- scratch (device globals; allocation-free) ----------
__device__ __align__(16) float gA_xz [NSEQ*LA*128];
__device__ __align__(16) float gA_dtT[NSEQ*64*LPA];
__device__ __align__(16) float gA_xsT[NSEQ*64*LPA];
__device__ __align__(16) float gA_zsT[NSEQ*64*LPA];
__device__ __align__(16) float gA_bcI[NSEQ*32*LPA];   // [n][tb][comp32][4]
__device__ __align__(16) float gA_yT [NSEQ*64*LTA];   // [n][ch][t]
__device__ __align__(16) float gA_o  [NSEQ*LTA*32];

__device__ __align__(16) float gB_xz0 [NSEQ*LB*96];
__device__ __align__(16) float gB_dtT0[NSEQ*48*LPB];
__device__ __align__(16) float gB_xsT0[NSEQ*48*LPB];
__device__ __align__(16) float gB_zsT0[NSEQ*48*LPB];
__device__ __align__(16) float gB_bcI0[NSEQ*32*LPB];
__device__ __align__(16) float gB_yT0 [NSEQ*48*LTB];
__device__ __align__(16) float gB_o0  [NSEQ*LTB*24];

__device__ __align__(16) float gB_xz1 [NSEQ*LB*96];
__device__ __align__(16) float gB_dtT1[NSEQ*48*LPB];
__device__ __align__(16) float gB_xsT1[NSEQ*48*LPB];
__device__ __align__(16) float gB_zsT1[NSEQ*48*LPB];
__device__ __align__(16) float gB_bcI1[NSEQ*32*LPB];
__device__ __align__(16) float gB_yT1 [NSEQ*48*LTB];
__device__ __align__(16) float gB_o1  [NSEQ*LTB*24];

template<int RUN> __device__ __forceinline__ float* bufXZ(){
  if constexpr (RUN==0) return gA_xz; else if constexpr (RUN==1) return gB_xz0; else return gB_xz1; }
template<int RUN> __device__ __forceinline__ float* bufDTT(){
  if constexpr (RUN==0) return gA_dtT; else if constexpr (RUN==1) return gB_dtT0; else return gB_dtT1; }
template<int RUN> __device__ __forceinline__ float* bufXST(){
  if constexpr (RUN==0) return gA_xsT; else if constexpr (RUN==1) return gB_xsT0; else return gB_xsT1; }
template<int RUN> __device__ __forceinline__ float* bufZST(){
  if constexpr (RUN==0) return gA_zsT; else if constexpr (RUN==1) return gB_zsT0; else return gB_zsT1; }
template<int RUN> __device__ __forceinline__ float* bufBCI(){
  if constexpr (RUN==0) return gA_bcI; else if constexpr (RUN==1) return gB_bcI0; else return gB_bcI1; }
template<int RUN> __device__ __forceinline__ float* bufYT(){
  if constexpr (RUN==0) return gA_yT; else if constexpr (RUN==1) return gB_yT0; else return gB_yT1; }
template<int RUN> __device__ __forceinline__ float* bufO(){
  if constexpr (RUN==0) return gA_o; else if constexpr (RUN==1) return gB_o0; else return gB_o1; }

__device__ __forceinline__ float warp_sum(float v){
  v += __shfl_xor_sync(0xffffffffu, v, 16);
  v += __shfl_xor_sync(0xffffffffu, v, 8);
  v += __shfl_xor_sync(0xffffffffu, v, 4);
  v += __shfl_xor_sync(0xffffffffu, v, 2);
  v += __shfl_xor_sync(0xffffffffu, v, 1);
  return v;
}
__device__ __forceinline__ float silu_f(float x){
  return __fdividef(x, 1.f + __expf(-x));
}

// ---------- packed f32x2 helpers ----------
__device__ __forceinline__ unsigned long long pack2(float lo, float hi){
  unsigned long long r;
  asm("mov.b64 %0, {%1, %2};" : "=l"(r) : "f"(lo), "f"(hi));
  return r;
}
__device__ __forceinline__ float2 unpack2(unsigned long long v){
  float2 f;
  asm("mov.b64 {%0, %1}, %2;" : "=f"(f.x), "=f"(f.y) : "l"(v));
  return f;
}
__device__ __forceinline__ void ffma2(unsigned long long &d, unsigned long long a, unsigned long long b){
  asm("fma.rn.f32x2 %0, %1, %2, %0;" : "+l"(d) : "l"(a), "l"(b));
}

// ============ K1: gather + layernorm + in_proj (FFMA2) ============
template<int RUN>
__global__ void __launch_bounds__(128) k_inproj(
    const float* __restrict__ x, const float* __restrict__ nw,
    const float* __restrict__ nb, const float* __restrict__ gt,
    const float* __restrict__ Win)
{
  constexpr int DM  = (RUN==0)?32:24;
  constexpr int DXZ = (RUN==0)?128:96;
  constexpr int LF  = (RUN==0)?LA:LB;
  constexpr int KO  = DXZ/32;
  __shared__ float Wtr[DM*128];                   // [d][lane][4] (k padded to 4)
  __shared__ __align__(16) float vsh[4][DM][8];

  int tid = threadIdx.x;
  for (int i = tid; i < DM*128; i += 128){
    int d = i >> 7, r = i & 127, ln = r >> 2, k = r & 3;
    Wtr[i] = (k < KO) ? Win[(k*32+ln)*DM + d] : 0.f;
  }
  int w = tid >> 5, lane = tid & 31;
  int n = blockIdx.y, bh = n >> 3, bw = n & 7;
  int t0 = (blockIdx.x*4 + w)*8;

  float v[8];
  #pragma unroll
  for (int tok = 0; tok < 8; tok++){
    int t = t0 + tok; float val = 0.f;
    if (lane < DM && t < LF){
      if (t == 0) val = gt[lane];
      else {
        int q = t - 1, addr;
        if (RUN == 0){
          int row = q / 48, col = q - row*48;
          int i0 = row >> 1, r1 = row & 1, j0 = col >> 1, r2 = col & 1;
          addr = (lane*4 + r1*2 + r2)*36864 + (bh*24 + i0)*192 + bw*24 + j0;
        } else if (RUN == 1){
          int c = q / 24, p = q - c*24;
          addr = c*36864 + (bh*24 + lane)*192 + bw*24 + p;
        } else {
          int c = q / 24, p = q - c*24;
          addr = c*36864 + (bh*24 + p)*192 + bw*24 + lane;
        }
        val = __ldg(x + addr);
      }
    }
    v[tok] = val;
  }
  float nwv = (lane < DM) ? nw[lane] : 0.f;
  float nbv = (lane < DM) ? nb[lane] : 0.f;
  #pragma unroll
  for (int tok = 0; tok < 8; tok++){
    float s  = warp_sum(v[tok]);
    float s2 = warp_sum(v[tok]*v[tok]);
    float m  = s * (1.f/DM);
    float var = s2 * (1.f/DM) - m*m;
    float vn = (v[tok] - m) * rsqrtf(var + 1e-5f) * nwv + nbv;
    if (lane < DM) vsh[w][lane][tok] = vn;
  }
  __syncthreads();

  unsigned long long accp[KO][4];
  #pragma unroll
  for (int k = 0; k < KO; k++)
    #pragma unroll
    for (int p = 0; p < 4; p++) accp[k][p] = 0ull;

  #pragma unroll 4
  for (int d = 0; d < DM; d++){
    const ulonglong2* vp = (const ulonglong2*)vsh[w][d];
    ulonglong2 va = vp[0], vb = vp[1];
    float4 wq = *(const float4*)&Wtr[(d*32+lane)*4];
    float wa[4] = {wq.x, wq.y, wq.z, wq.w};
    #pragma unroll
    for (int k = 0; k < KO; k++){
      unsigned long long wp = pack2(wa[k], wa[k]);
      ffma2(accp[k][0], wp, va.x);
      ffma2(accp[k][1], wp, va.y);
      ffma2(accp[k][2], wp, vb.x);
      ffma2(accp[k][3], wp, vb.y);
    }
  }
  float* xz = bufXZ<RUN>();
  #pragma unroll
  for (int p = 0; p < 4; p++){
    float2 f[KO];
    #pragma unroll
    for (int k = 0; k < KO; k++) f[k] = unpack2(accp[k][p]);
    #pragma unroll
    for (int e = 0; e < 2; e++){
      int t = t0 + 2*p + e;
      if (t < LF){
        float* op = xz + (n*LF + t)*DXZ + lane;
        #pragma unroll
        for (int k = 0; k < KO; k++) op[32*k] = e ? f[k].y : f[k].x;
      }
    }
  }
}

// ============ K2: conv + silu + x_proj + dt (FFMA2 xproj) ============
template<int RUN>
__global__ void __launch_bounds__(256) k_convxp(
  const float* __restrict__ convw, const float* __restrict__ convb,
  const float* __restrict__ Wx,    const float* __restrict__ dtw,
  const float* __restrict__ dtb)
{
  constexpr int DIN = (RUN==0)?64:48;
  constexpr int DXZ = 2*DIN;
  constexpr int LF  = (RUN==0)?LA:LB;
  constexpr int LFP = (RUN==0)?LPA:LPB;
  const float* xz = bufXZ<RUN>();
  float* xsT = bufXST<RUN>();
  float* zsT = bufZST<RUN>();
  float* dtT = bufDTT<RUN>();
  float* bcI = bufBCI<RUN>();

  __shared__ float Wxt[DIN*34];          // [d][o]
  __shared__ __align__(16) float xs_s[DIN][34];
  __shared__ __align__(16) float zs_s[DIN][34];
  __shared__ __align__(16) float dt_s[DIN][34];
  __shared__ float bc_s[32][33];

  int tid = threadIdx.x;
  for (int i = tid; i < 34*DIN; i += 256){
    int o = i / DIN, d = i - o*DIN;
    Wxt[d*34 + o] = Wx[i];
  }
  int w = tid >> 5, lane = tid & 31;
  int n = blockIdx.y;
  int tile0 = blockIdx.x*32;
  int t0 = tile0 + w*4;

  float cw[2][4], cb[2], w0c[2], w1c[2], db[2];
  #pragma unroll
  for (int kk = 0; kk < 2; kk++){
    int ch = lane + 32*kk;
    bool ok = ch < DIN;
    #pragma unroll
    for (int k = 0; k < 4; k++) cw[kk][k] = ok ? convw[ch*4+k] : 0.f;
    cb[kk]  = ok ? convb[ch]   : 0.f;
    w0c[kk] = ok ? dtw[ch*2+0] : 0.f;
    w1c[kk] = ok ? dtw[ch*2+1] : 0.f;
    db[kk]  = ok ? dtb[ch]     : 0.f;
  }
  #pragma unroll
  for (int tok = 0; tok < 4; tok++){
    int t = t0 + tok;
    bool valid = t < LF;
    #pragma unroll
    for (int kk = 0; kk < 2; kk++){
      int ch = lane + 32*kk;
      if (ch < DIN){
        float a = cb[kk];
        float zval = 0.f;
        if (valid){
          #pragma unroll
          for (int k = 0; k < 4; k++){
            int ts = t + k - 3;
            if (ts >= 0) a = fmaf(xz[(n*LF + ts)*DXZ + ch], cw[kk][k], a);
          }
          zval = xz[(n*LF + t)*DXZ + DIN + ch];
        }
        xs_s[ch][w*4+tok] = silu_f(a);
        zs_s[ch][w*4+tok] = silu_f(zval);
      }
    }
  }
  __syncthreads();   // Wxt + xs_s ready

  unsigned long long ap0=0ull, ap1=0ull, a2p0=0ull, a2p1=0ull;
  #pragma unroll 8
  for (int d = 0; d < DIN; d++){
    const unsigned long long* xp = (const unsigned long long*)&xs_s[d][w*4];
    unsigned long long x01 = xp[0], x23 = xp[1];
    float wv = Wxt[d*34 + lane];
    unsigned long long wp = pack2(wv, wv);
    ffma2(ap0, wp, x01);
    ffma2(ap1, wp, x23);
    if (lane < 2){
      float w2 = Wxt[d*34 + 32 + lane];
      unsigned long long wp2 = pack2(w2, w2);
      ffma2(a2p0, wp2, x01);
      ffma2(a2p1, wp2, x23);
    }
  }
  float2 u0 = unpack2(ap0), u1 = unpack2(ap1);
  float acc[4]  = {u0.x, u0.y, u1.x, u1.y};
  float2 q0 = unpack2(a2p0), q1 = unpack2(a2p1);
  float acc2[4] = {q0.x, q0.y, q1.x, q1.y};

  #pragma unroll
  for (int tok = 0; tok < 4; tok++){
    float d0 = __shfl_sync(0xffffffffu, acc[tok], 0);
    float d1 = __shfl_sync(0xffffffffu, acc[tok], 1);
    #pragma unroll
    for (int kk = 0; kk < 2; kk++){
      int ch = lane + 32*kk;
      if (ch < DIN){
        float r = fmaf(w0c[kk], d0, fmaf(w1c[kk], d1, db[kk]));
        dt_s[ch][w*4+tok] = fmaxf(r, 0.f) + __logf(1.f + __expf(-fabsf(r)));
      }
    }
    if (lane >= 2) bc_s[lane-2][w*4+tok]  = acc[tok];
    else           bc_s[30+lane][w*4+tok] = acc2[tok];
  }
  __syncthreads();

  // coalesced flush: consecutive threads -> consecutive float4 along t
  for (int i = tid; i < DIN*8; i += 256){
    int ch = i >> 3, v = i & 7;
    int tt = tile0 + 4*v;
    size_t off = (size_t)(n*DIN + ch)*LFP + tt;
    *(float4*)(xsT + off) = make_float4(xs_s[ch][4*v],xs_s[ch][4*v+1],xs_s[ch][4*v+2],xs_s[ch][4*v+3]);
    *(float4*)(zsT + off) = make_float4(zs_s[ch][4*v],zs_s[ch][4*v+1],zs_s[ch][4*v+2],zs_s[ch][4*v+3]);
    *(float4*)(dtT + off) = make_float4(dt_s[ch][4*v],dt_s[ch][4*v+1],dt_s[ch][4*v+2],dt_s[ch][4*v+3]);
  }
  // bc interleaved flush: [n][tb][comp][4]
  {
    int tbl = tid >> 5, comp = tid & 31;
    float4 bv = make_float4(bc_s[comp][4*tbl],bc_s[comp][4*tbl+1],bc_s[comp][4*tbl+2],bc_s[comp][4*tbl+3]);
    *(float4*)(bcI + ((size_t)(n*(LFP/4) + tile0/4 + tbl)*32 + comp)*4) = bv;
  }
}

// ============ K3: selective scan (8 lanes/ch, 2 states/lane, 8 tok/iter) ============
template<int L, int DIN, int LFP, int LT>
__device__ __forceinline__ void scan8u2(
  const float* __restrict__ dtT, const float* __restrict__ xsT,
  const float* __restrict__ zsT, const float* __restrict__ bcI,
  float* __restrict__ yT, const float* __restrict__ alog,
  const float* __restrict__ Dv, int n, int ch4, int lane)
{
  int g = lane >> 3, s = lane & 7;
  int ch = ch4 + g;
  const float* dtp = dtT + (size_t)(n*DIN + ch)*LFP;
  const float* xsp = xsT + (size_t)(n*DIN + ch)*LFP;
  const float* zsp = zsT + (size_t)(n*DIN + ch)*LFP;
  const float* bcn = bcI + (size_t)n*(LFP/4)*128;
  float A0 = -expf(__ldg(alog + ch*16 + 2*s));
  float A1 = -expf(__ldg(alog + ch*16 + 2*s + 1));
  float Dd = __ldg(Dv + ch);
  float* yTp = yT + (size_t)(n*DIN + ch)*LT;
  bool yl = (s == 0);
  float h0 = 0.f, h1 = 0.f;
  float yb0=0.f, yb1=0.f, yb2=0.f;

  auto step4 = [&](float4 dq, float4 uq, float4 B0q, float4 B1q,
                   float4 C0q, float4 C1q, float4 zv, int tcur, bool flushOK){
    float da[4]  = {dq.x,dq.y,dq.z,dq.w};
    float ua[4]  = {uq.x,uq.y,uq.z,uq.w};
    float B0a[4] = {B0q.x,B0q.y,B0q.z,B0q.w};
    float B1a[4] = {B1q.x,B1q.y,B1q.z,B1q.w};
    float C0a[4] = {C0q.x,C0q.y,C0q.z,C0q.w};
    float C1a[4] = {C1q.x,C1q.y,C1q.z,C1q.w};
    float za[4]  = {zv.x,zv.y,zv.z,zv.w};
    #pragma unroll
    for (int j = 0; j < 4; j++){
      float a0 = __expf(da[j]*A0);
      float a1 = __expf(da[j]*A1);
      float du = da[j]*ua[j];
      h0 = fmaf(h0, a0, du*B0a[j]);
      h1 = fmaf(h1, a1, du*B1a[j]);
      float acc = fmaf(h1, C1a[j], h0*C0a[j]);
      acc += __shfl_xor_sync(0xffffffffu, acc, 1);
      acc += __shfl_xor_sync(0xffffffffu, acc, 2);
      acc += __shfl_xor_sync(0xffffffffu, acc, 4);
      if (yl){
        float val = fmaf(ua[j], Dd, acc) * za[j];
        if (j == 0){
          if (flushOK) *(float4*)(yTp + tcur - 4) = make_float4(yb0, yb1, yb2, val);
        } else if (j == 1) yb0 = val;
        else if (j == 2)   yb1 = val;
        else               yb2 = val;
      }
    }
  };

  constexpr int NB2 = (L-1)/8;
  for (int tb = 0; tb < NB2; tb++){
    int t = tb*8;
    size_t bo0 = (size_t)(2*tb)*128, bo1 = (size_t)(2*tb+1)*128;
    float4 dqa  = __ldg((const float4*)(dtp + t));
    float4 dqb  = __ldg((const float4*)(dtp + t + 4));
    float4 uqa  = __ldg((const float4*)(xsp + t));
    float4 uqb  = __ldg((const float4*)(xsp + t + 4));
    float4 B0qa = __ldg((const float4*)(bcn + bo0 + (2*s)*4));
    float4 B1qa = __ldg((const float4*)(bcn + bo0 + (2*s+1)*4));
    float4 C0qa = __ldg((const float4*)(bcn + bo0 + 64 + (2*s)*4));
    float4 C1qa = __ldg((const float4*)(bcn + bo0 + 64 + (2*s+1)*4));
    float4 B0qb = __ldg((const float4*)(bcn + bo1 + (2*s)*4));
    float4 B1qb = __ldg((const float4*)(bcn + bo1 + (2*s+1)*4));
    float4 C0qb = __ldg((const float4*)(bcn + bo1 + (2*s)*4 + 64));
    float4 C1qb = __ldg((const float4*)(bcn + bo1 + (2*s+1)*4 + 64));
    float4 zva = make_float4(0,0,0,0), zvb = make_float4(0,0,0,0);
    if (yl){
      zva = __ldg((const float4*)(zsp + t));
      zvb = __ldg((const float4*)(zsp + t + 4));
    }
    step4(dqa, uqa, B0qa, B1qa, C0qa, C1qa, zva, t,     tb > 0);
    step4(dqb, uqb, B0qb, B1qb, C0qb, C1qb, zvb, t + 4, true);
  }
  { // tail: step t = L-1
    constexpr int t = L-1;
    constexpr size_t bo = (size_t)((L-1)/4)*128;
    float dtv = __ldg(dtp + t), u = __ldg(xsp + t);
    float B0 = __ldg(bcn + bo + (2*s)*4);
    float B1 = __ldg(bcn + bo + (2*s+1)*4);
    float C0 = __ldg(bcn + bo + 64 + (2*s)*4);
    float C1 = __ldg(bcn + bo + 64 + (2*s+1)*4);
    float a0 = __expf(dtv*A0);
    float a1 = __expf(dtv*A1);
    float du = dtv*u;
    h0 = fmaf(h0, a0, du*B0);
    h1 = fmaf(h1, a1, du*B1);
    float acc = fmaf(h1, C1, h0*C0);
    acc += __shfl_xor_sync(0xffffffffu, acc, 1);
    acc += __shfl_xor_sync(0xffffffffu, acc, 2);
    acc += __shfl_xor_sync(0xffffffffu, acc, 4);
    if (yl){
      float val = fmaf(u, Dd, acc) * __ldg(zsp + t);
      *(float4*)(yTp + L - 5) = make_float4(yb0, yb1, yb2, val);
    }
  }
}

__global__ void __launch_bounds__(128) k_scanA(
  const float* __restrict__ alogA, const float* __restrict__ DA)
{
  int wg = (blockIdx.x*128 + threadIdx.x) >> 5;   // 0..1023
  int lane = threadIdx.x & 31;
  int n = wg >> 4, ch4 = (wg & 15)*4;             // 16 warps/seq, 4 ch/warp
  scan8u2<LA,64,LPA,LTA>(gA_dtT, gA_xsT, gA_zsT, gA_bcI, gA_yT, alogA, DA, n, ch4, lane);
}

template<int R>
__global__ void __launch_bounds__(128) k_scanB(
  const float* __restrict__ alogB, const float* __restrict__ DB)
{
  int wg = (blockIdx.x*128 + threadIdx.x) >> 5;   // 0..767
  int lane = threadIdx.x & 31;
  int n = wg/12, ch4 = (wg - n*12)*4;             // 12 warps/seq, 4 ch/warp
  if (R == 0)
    scan8u2<LB,48,LPB,LTB>(gB_dtT0, gB_xsT0, gB_zsT0, gB_bcI0, gB_yT0, alogB, DB, n, ch4, lane);
  else
    scan8u2<LB,48,LPB,LTB>(gB_dtT1, gB_xsT1, gB_zsT1, gB_bcI1, gB_yT1, alogB, DB, n, ch4, lane);
}

// ============ K4: out_proj (transposed y via smem tile, FFMA2) ============
template<int RUN>
__global__ void __launch_bounds__(256) k_outproj(const float* __restrict__ Wo)
{
  constexpr int DIN = (RUN==0)?64:48;
  constexpr int DM  = (RUN==0)?32:24;
  constexpr int LT  = (RUN==0)?LTA:LTB;
  const float* yT = bufYT<RUN>();
  float* o = bufO<RUN>();
  __shared__ float Wt[DIN*32];
  __shared__ __align__(16) float y_s[DIN][34];
  int tid = threadIdx.x;
  for (int i = tid; i < DIN*32; i += 256){
    int d = i >> 5, oo = i & 31;
    Wt[i] = (oo < DM) ? Wo[oo*DIN + d] : 0.f;
  }
  int w = tid >> 5, lane = tid & 31;
  int n = blockIdx.y;
  int tile0 = blockIdx.x*32;
  for (int i = tid; i < DIN*8; i += 256){
    int ch = i >> 3, v = i & 7;
    float4 yv = *(const float4*)(yT + (size_t)(n*DIN + ch)*LT + tile0 + 4*v);
    y_s[ch][4*v+0] = yv.x; y_s[ch][4*v+1] = yv.y;
    y_s[ch][4*v+2] = yv.z; y_s[ch][4*v+3] = yv.w;
  }
  __syncthreads();
  unsigned long long ap0=0ull, ap1=0ull;
  #pragma unroll 8
  for (int d = 0; d < DIN; d++){
    const unsigned long long* yp2 = (const unsigned long long*)&y_s[d][w*4];
    unsigned long long y01 = yp2[0], y23 = yp2[1];
    float wv = Wt[d*32 + lane];
    unsigned long long wp = pack2(wv, wv);
    ffma2(ap0, wp, y01);
    ffma2(ap1, wp, y23);
  }
  float2 u0 = unpack2(ap0), u1 = unpack2(ap1);
  float acc[4] = {u0.x, u0.y, u1.x, u1.y};
  if (lane < DM){
    #pragma unroll
    for (int tok = 0; tok < 4; tok++){
      int t = tile0 + w*4 + tok;
      o[(size_t)(n*LT + t)*DM + lane] = acc[tok];
    }
  }
}

// ============ K5: combine into output (4 outputs/thread, STG.128) ============
__global__ void __launch_bounds__(256) k_combine(float* __restrict__ out)
{
  int base = (blockIdx.x*256 + threadIdx.x)*4;
  if (base >= 128*192*192) return;
  float r[4];
  #pragma unroll
  for (int e = 0; e < 4; e++){
    int idx = base + e;
    int c = idx / 36864;
    int rem = idx - c*36864;
    int n = rem / 576;
    int rem2 = rem - n*576;
    int i = rem2 / 24;
    int j = rem2 - i*24;
    int d = c >> 2, r1 = (c >> 1) & 1, r2 = c & 1;
    float v0 = __ldg(&gA_o [(size_t)(n*2304 + (2*i+r1)*48 + 2*j + r2)*32 + d]);
    float v1 = __ldg(&gB_o0[(size_t)(n*3072 + c*24 + j)*24 + i]);
    float v2 = __ldg(&gB_o1[(size_t)(n*3072 + c*24 + i)*24 + j]);
    r[e] = (v0 + v1 + v2) * (1.f/3.f);
  }
  *(float4*)(out + base) = make_float4(r[0], r[1], r[2], r[3]);
}

// ============ host launch (3-stream overlapped pipeline) ============
static cudaStream_t g_s1, g_s2;
static cudaEvent_t  g_fork, g_j1, g_j2;
static int g_init = 0;

extern "C" void kernel_launch(void* const* d_in, const int* in_sizes, int n_in,
                              void* d_out, int out_size) {
  (void)in_sizes; (void)n_in; (void)out_size;
  const float* X   = (const float*)d_in[0];
  const float* NW  = (const float*)d_in[1];
  const float* NB  = (const float*)d_in[2];
  const float* N2W = (const float*)d_in[3];
  const float* N2B = (const float*)d_in[4];
  const float* GT1 = (const float*)d_in[5];
  const float* GT2 = (const float*)d_in[6];
  const float* M1_IN  = (const float*)d_in[7];
  const float* M1_CW  = (const float*)d_in[8];
  const float* M1_CB  = (const float*)d_in[9];
  const float* M1_XW  = (const float*)d_in[10];
  const float* M1_DTW = (const float*)d_in[11];
  const float* M1_DTB = (const float*)d_in[12];
  const float* M1_AL  = (const float*)d_in[13];
  const float* M1_D   = (const float*)d_in[14];
  const float* M1_OW  = (const float*)d_in[15];
  const float* M2_IN  = (const float*)d_in[16];
  const float* M2_CW  = (const float*)d_in[17];
  const float* M2_CB  = (const float*)d_in[18];
  const float* M2_XW  = (const float*)d_in[19];
  const float* M2_DTW = (const float*)d_in[20];
  const float* M2_DTB = (const float*)d_in[21];
  const float* M2_AL  = (const float*)d_in[22];
  const float* M2_D   = (const float*)d_in[23];
  const float* M2_OW  = (const float*)d_in[24];

  if (!g_init){
    cudaStreamCreateWithFlags(&g_s1, cudaStreamNonBlocking);
    cudaStreamCreateWithFlags(&g_s2, cudaStreamNonBlocking);
    cudaEventCreateWithFlags(&g_fork, cudaEventDisableTiming);
    cudaEventCreateWithFlags(&g_j1,   cudaEventDisableTiming);
    cudaEventCreateWithFlags(&g_j2,   cudaEventDisableTiming);
    g_init = 1;
  }

  // fork side streams off the (possibly capturing) legacy stream
  cudaEventRecord(g_fork, 0);
  cudaStreamWaitEvent(g_s1, g_fork, 0);
  cudaStreamWaitEvent(g_s2, g_fork, 0);

  // chain A on the legacy stream
  k_inproj<0><<<dim3(73, 64), 128>>>(X, NW, NB, GT1, M1_IN);
  k_convxp<0><<<dim3(73, 64), 256>>>(M1_CW, M1_CB, M1_XW, M1_DTW, M1_DTB);
  k_scanA<<<256, 128>>>(M1_AL, M1_D);
  k_outproj<0><<<dim3(72, 64), 256>>>(M1_OW);

  // chain B0 on s1
  k_inproj<1><<<dim3(97, 64), 128, 0, g_s1>>>(X, N2W, N2B, GT2, M2_IN);
  k_convxp<1><<<dim3(97, 64), 256, 0, g_s1>>>(M2_CW, M2_CB, M2_XW, M2_DTW, M2_DTB);
  k_scanB<0><<<192, 128, 0, g_s1>>>(M2_AL, M2_D);
  k_outproj<1><<<dim3(96, 64), 256, 0, g_s1>>>(M2_OW);
  cudaEventRecord(g_j1, g_s1);

  // chain B1 on s2
  k_inproj<2><<<dim3(97, 64), 128, 0, g_s2>>>(X, N2W, N2B, GT2, M2_IN);
  k_convxp<2><<<dim3(97, 64), 256, 0, g_s2>>>(M2_CW, M2_CB, M2_XW, M2_DTW, M2_DTB);
  k_scanB<1><<<192, 128, 0, g_s2>>>(M2_AL, M2_D);
  k_outproj<2><<<dim3(96, 64), 256, 0, g_s2>>>(M2_OW);
  cudaEventRecord(g_j2, g_s2);

  // join and combine on the legacy stream
  cudaStreamWaitEvent(0, g_j1, 0);
  cudaStreamWaitEvent(0, g_j2, 0);
  k_combine<<<4608, 256>>>((float*)d_out);
}